// round 9
// baseline (speedup 1.0000x reference)
#include <cuda_runtime.h>
#include <cuda_bf16.h>
#include <mma.h>
#include <cstdint>

using namespace nvcuda;

#define NN 8192
#define DD 64
#define MAXDEG 16
#define KK 8
#define LL 17            // MAXDEG + 1
#define DIN 128          // D * EXPAND
#define EPS 1e-5f

#define NODES_TILE 3
#define TROWS 64                          // padded rows per tile (51 valid)
#define TILES ((NN + NODES_TILE - 1)/NODES_TILE)   // 2731

// ---------------- device scratch ----------------
__device__ float g_hflat[NN*MAXDEG*DD];
__device__ float g_hinput[NN*LL*DD];
__device__ float g_y[NN*LL*DD];
__device__ float g_bnsum[DD];
__device__ float g_bnsq[DD];
__device__ __nv_bfloat16 g_w1thi[64*256];   // fc1_w^T [k][ch] hi
__device__ __nv_bfloat16 g_w1tlo[64*256];   // lo
__device__ __nv_bfloat16 g_w2thi[128*64];   // fc2_w^T [c][d] hi
__device__ __nv_bfloat16 g_w2tlo[128*64];   // lo

__device__ __forceinline__ float sigm(float x) { return 1.f/(1.f+__expf(-x)); }

// smem byte offsets (per-CTA, dynamic)
#define SO_A    0        // 32768: fc1 z out fp32 [64][128] -> silu(z) in place; D2 aliases [0:16384)
#define SO_B    32768    // 32768: fc1 x out fp32 [64][128]
#define SO_HHI  65536    // 8192: H hi bf16 [64][64]   (dead after fc1 -> G overwrites)
#define SO_HLO  73728    // 8192: H lo
#define SO_GHI  65536    // 16384: G hi bf16 [64][128]
#define SO_GLO  81920    // 16384: G lo
#define SO_D2   0        // 16384: fc2 out fp32 [64][64] (aliases A)
#define SO_RR   98304    // 256
#define SO_BNP  98560    // 2048
#define SMEM3   100608

// ---------------- K0: zero BN accumulators (graph replays!) ----------------
__global__ void kz() {
    int t = threadIdx.x;
    if (t < DD) { g_bnsum[t] = 0.f; g_bnsq[t] = 0.f; }
}

// ---------------- KW: transposed hi/lo weight images ----------------
__global__ void kw(const float* __restrict__ fc1w, const float* __restrict__ fc2w) {
    int i = blockIdx.x*256 + threadIdx.x;   // grid 96 -> 24576
    if (i < 16384) {
        int ch = i >> 6, k = i & 63;
        float v = fc1w[i];
        __nv_bfloat16 hi = __float2bfloat16(v);
        g_w1thi[k*256 + ch] = hi;
        g_w1tlo[k*256 + ch] = __float2bfloat16(v - __bfloat162float(hi));
    } else if (i < 24576) {
        int j = i - 16384;
        int d = j >> 7, c = j & 127;
        float v = fc2w[j];
        __nv_bfloat16 hi = __float2bfloat16(v);
        g_w2thi[c*64 + d] = hi;
        g_w2tlo[c*64 + d] = __float2bfloat16(v - __bfloat162float(hi));
    }
}

// ---------------- K1: message + mailbox rank-sort ----------------
__global__ void k1(const float* __restrict__ hs, const float* __restrict__ hs_e,
                   const float* __restrict__ degree, const float* __restrict__ noise) {
    int n = blockIdx.x*4 + (threadIdx.x >> 6);
    int d = threadIdx.x & 63;
    float h = hs[n*DD + d];
    float deg = __ldg(&degree[n]);
    float sc[KK];
#pragma unroll
    for (int k = 0; k < KK; k++) sc[k] = deg + __ldg(&noise[n*KK + k]);
#pragma unroll
    for (int k = 0; k < KK; k++) {
        float e = hs_e[(n*KK + k)*DD + d];
        float m = h * sigm(e);
        int r = 0;
#pragma unroll
        for (int j = 0; j < KK; j++)
            r += (sc[j] < sc[k]) || (sc[j] == sc[k] && j < k);
        g_hflat[n*(MAXDEG*DD) + r*DD + d] = m;
    }
#pragma unroll
    for (int j = KK; j < MAXDEG; j++)
        g_hflat[n*(MAXDEG*DD) + j*DD + d] = 0.f;
}

// ---------------- K2: (A+I) spmm gather ----------------
__global__ void k2(const float* __restrict__ hs, const int* __restrict__ src) {
    int n = blockIdx.x;
    int t = threadIdx.x;
    if (t < DD) g_hinput[n*(LL*DD) + t] = hs[n*DD + t];
    float4 a = ((const float4*)(g_hflat + n*(MAXDEG*DD)))[t];
#pragma unroll
    for (int k = 0; k < KK; k++) {
        int s = __ldg(&src[n*KK + k]);
        float4 v = ((const float4*)(g_hflat + s*(MAXDEG*DD)))[t];
        a.x += v.x; a.y += v.y; a.z += v.z; a.w += v.w;
    }
    ((float4*)(g_hinput + n*(LL*DD) + DD))[t] = a;
}

// fc1 half-GEMM: dst[64][128] = H[64][64] x W1T[:, chofs:chofs+128], hi/lo 3-pass
__device__ __forceinline__ void fc1_half(
    float* dst, const __nv_bfloat16* hhi, const __nv_bfloat16* hlo,
    int chofs, int w)
{
    int rt = w & 3;
    int ctb = (w >> 2) * 4;     // 4 ct-tiles of 16 per warp
    wmma::fragment<wmma::accumulator, 16, 16, 16, float> acc[4];
#pragma unroll
    for (int j = 0; j < 4; j++) wmma::fill_fragment(acc[j], 0.f);
#pragma unroll 1
    for (int p = 0; p < 3; p++) {
        const __nv_bfloat16* ap = (p == 1) ? hlo : hhi;
        const __nv_bfloat16* wp = (p == 2) ? g_w1tlo : g_w1thi;
#pragma unroll
        for (int ks = 0; ks < 4; ks++) {
            wmma::fragment<wmma::matrix_a, 16, 16, 16, __nv_bfloat16, wmma::row_major> af;
            wmma::load_matrix_sync(af, ap + rt*16*64 + ks*16, 64);
#pragma unroll
            for (int j = 0; j < 4; j++) {
                wmma::fragment<wmma::matrix_b, 16, 16, 16, __nv_bfloat16, wmma::row_major> bf;
                wmma::load_matrix_sync(bf, wp + ks*16*256 + chofs + (ctb + j)*16, 256);
                wmma::mma_sync(acc[j], af, bf, acc[j]);
            }
        }
    }
#pragma unroll
    for (int j = 0; j < 4; j++)
        wmma::store_matrix_sync(dst + rt*16*128 + (ctb + j)*16, acc[j], 128, wmma::mem_row_major);
}

// ---------------- K3: wmma bf16 hi/lo GatedCNN (2 CTAs/SM) ----------------
__global__ void __launch_bounds__(256, 2)
k3(const float* __restrict__ fc1b, const float* __restrict__ convw,
   const float* __restrict__ convb, const float* __restrict__ fc2b,
   const float* __restrict__ rmsw) {
    extern __shared__ char sm[];
    float* bufA = (float*)(sm + SO_A);
    float* bufB = (float*)(sm + SO_B);
    __nv_bfloat16* hhi = (__nv_bfloat16*)(sm + SO_HHI);
    __nv_bfloat16* hlo = (__nv_bfloat16*)(sm + SO_HLO);
    __nv_bfloat16* ghi = (__nv_bfloat16*)(sm + SO_GHI);
    __nv_bfloat16* glo = (__nv_bfloat16*)(sm + SO_GLO);
    float* d2  = (float*)(sm + SO_D2);
    float* rr  = (float*)(sm + SO_RR);
    float* bnp = (float*)(sm + SO_BNP);

    int t = threadIdx.x;
    int w = t >> 5;

    int n0 = blockIdx.x * NODES_TILE;
    int nvalid = min(NODES_TILE, NN - n0);
    int rvalid = nvalid * LL;
    const float* hsrc = g_hinput + (size_t)n0*(LL*DD);

    // ---- stage H tile (hi/lo bf16, row-major [64][64]) ----
    {
        int vmax = rvalid * DD;
        for (int i = t; i < TROWS*DD; i += 256) {
            float v = (i < vmax) ? hsrc[i] : 0.f;
            __nv_bfloat16 hi = __float2bfloat16(v);
            hhi[i] = hi;
            hlo[i] = __float2bfloat16(v - __bfloat162float(hi));
        }
    }
    __syncthreads();

    // ---- fc1 z-half -> A ----
    fc1_half(bufA, hhi, hlo, DIN, w);
    __syncthreads();

    // ---- silu(z + b1z) in place on A ----
#pragma unroll
    for (int i = t; i < TROWS*DIN; i += 256) {
        float z = bufA[i] + __ldg(&fc1b[DIN + (i & 127)]);
        bufA[i] = z * sigm(z);
    }

    // ---- fc1 x-half -> B (no sync needed: B,H untouched by silu pass) ----
    fc1_half(bufB, hhi, hlo, 0, w);
    __syncthreads();

    // ---- conv + gate -> G hi/lo (overwrites dead H region) ----
    {
        int c = t & 127;
        int rh = t >> 7;
        float cw0 = __ldg(&convw[c*4+0]), cw1 = __ldg(&convw[c*4+1]);
        float cw2 = __ldg(&convw[c*4+2]), cw3 = __ldg(&convw[c*4+3]);
        float cb  = __ldg(&convb[c]);
        float b1x = __ldg(&fc1b[c]);
#pragma unroll 1
        for (int ri = 0; ri < 32; ri++) {
            int r = rh*32 + ri;
            float gv = 0.f;
            if (r < rvalid) {
                int l = r % LL;
                float xc = cb + (bufB[r*DIN + c] + b1x)*cw3;
                if (l >= 1) xc += (bufB[(r-1)*DIN + c] + b1x)*cw2;
                if (l >= 2) xc += (bufB[(r-2)*DIN + c] + b1x)*cw1;
                if (l >= 3) xc += (bufB[(r-3)*DIN + c] + b1x)*cw0;
                gv = (xc*sigm(xc)) * bufA[r*DIN + c];
            }
            __nv_bfloat16 hi = __float2bfloat16(gv);
            ghi[r*DIN + c] = hi;
            glo[r*DIN + c] = __float2bfloat16(gv - __bfloat162float(hi));
        }
    }
    __syncthreads();

    // ---- fc2: D2[64][64] = G[64][128] x W2T[128][64], 3-pass (D2 aliases dead A) ----
    {
        int rt = w & 3;
        int ctb = (w >> 2) * 2;
        wmma::fragment<wmma::accumulator, 16, 16, 16, float> acc2[2];
#pragma unroll
        for (int j = 0; j < 2; j++) wmma::fill_fragment(acc2[j], 0.f);
#pragma unroll 1
        for (int p = 0; p < 3; p++) {
            const __nv_bfloat16* ap = (p == 1) ? glo : ghi;
            const __nv_bfloat16* wp = (p == 2) ? g_w2tlo : g_w2thi;
#pragma unroll
            for (int ks = 0; ks < 8; ks++) {
                wmma::fragment<wmma::matrix_a, 16, 16, 16, __nv_bfloat16, wmma::row_major> af;
                wmma::load_matrix_sync(af, ap + rt*16*DIN + ks*16, DIN);
#pragma unroll
                for (int j = 0; j < 2; j++) {
                    wmma::fragment<wmma::matrix_b, 16, 16, 16, __nv_bfloat16, wmma::row_major> bf;
                    wmma::load_matrix_sync(bf, wp + ks*16*64 + (ctb + j)*16, 64);
                    wmma::mma_sync(acc2[j], af, bf, acc2[j]);
                }
            }
        }
#pragma unroll
        for (int j = 0; j < 2; j++)
            wmma::store_matrix_sync(d2 + rt*16*64 + (ctb + j)*16, acc2[j], 64, wmma::mem_row_major);
    }
    __syncthreads();

    // ---- fc2 bias ----
#pragma unroll
    for (int i = t; i < TROWS*DD; i += 256) d2[i] += __ldg(&fc2b[i & 63]);
    __syncthreads();

    // ---- rms per row (staggered reads) ----
    if (t < rvalid) {
        const float* row = d2 + t*DD;
        float s = 0.f;
#pragma unroll
        for (int dd = 0; dd < DD; dd++) { float v = row[(dd + t) & 63]; s += v*v; }
        rr[t] = rsqrtf(s * (1.f/DD) + EPS);
    }
    __syncthreads();

    // ---- y = rmsnorm*rms_w + h_input; BN partials ----
    {
        int dch = t & 63;
        int r0 = (t >> 6) * 16;
        float rw = __ldg(&rmsw[dch]);
        float bsum = 0.f, bsq = 0.f;
        float* ydst = g_y + (size_t)n0*(LL*DD);
#pragma unroll
        for (int ri = 0; ri < 16; ri++) {
            int r = r0 + ri;
            if (r < rvalid) {
                float v = d2[r*DD + dch] * rr[r] * rw + hsrc[r*DD + dch];
                ydst[r*DD + dch] = v;
                bsum += v; bsq += v*v;
            }
        }
        bnp[t] = bsum;
        bnp[256 + t] = bsq;
    }
    __syncthreads();
    if (t < DD) {
        float s  = bnp[t] + bnp[t+64] + bnp[t+128] + bnp[t+192];
        float s2 = bnp[256+t] + bnp[256+t+64] + bnp[256+t+128] + bnp[256+t+192];
        atomicAdd(&g_bnsum[t], s);
        atomicAdd(&g_bnsq[t], s2);
    }
}

// ---------------- K5: BN apply + ReLU6 + L-aggregation + residual ----------------
__global__ void k5(const float* __restrict__ hs, const float* __restrict__ gamma,
                   const float* __restrict__ beta, const float* __restrict__ aggw,
                   const float* __restrict__ aggb, float* __restrict__ out) {
    int idx = blockIdx.x*256 + threadIdx.x;
    int d = idx & 63;
    float cnt = (float)(NN*LL);
    float mean = g_bnsum[d] / cnt;
    float var  = g_bnsq[d] / cnt - mean*mean;
    float is = rsqrtf(var + EPS);
    float ga = __ldg(&gamma[d]) * is;
    float be = __ldg(&beta[d]) - mean * ga;
    const float* yrow = g_y + (size_t)(idx >> 6)*(LL*DD);
    float s = __ldg(&aggb[0]);
#pragma unroll
    for (int l = 0; l < LL; l++) {
        float v = yrow[l*DD + d] * ga + be;
        v = fminf(fmaxf(v, 0.f), 6.f);
        s += v * __ldg(&aggw[l]);
    }
    out[idx] = s + hs[idx];
}

// ---------------- host ----------------
extern "C" void kernel_launch(void* const* d_in, const int* in_sizes, int n_in,
                              void* d_out, int out_size) {
    const float* hs     = (const float*)d_in[0];
    const float* hs_e   = (const float*)d_in[1];
    const float* degree = (const float*)d_in[2];
    const float* noise  = (const float*)d_in[3];
    const float* fc1w   = (const float*)d_in[4];
    const float* fc1b   = (const float*)d_in[5];
    const float* convw  = (const float*)d_in[6];
    const float* convb  = (const float*)d_in[7];
    const float* fc2w   = (const float*)d_in[8];
    const float* fc2b   = (const float*)d_in[9];
    const float* rmsw   = (const float*)d_in[10];
    const float* gamma  = (const float*)d_in[11];
    const float* beta   = (const float*)d_in[12];
    const float* aggw   = (const float*)d_in[13];
    const float* aggb   = (const float*)d_in[14];
    const int*   src    = (const int*)d_in[15];
    float* out = (float*)d_out;

    cudaFuncSetAttribute(k3, cudaFuncAttributeMaxDynamicSharedMemorySize, SMEM3);

    kz<<<1, 64>>>();
    kw<<<96, 256>>>(fc1w, fc2w);
    k1<<<NN/4, 256>>>(hs, hs_e, degree, noise);
    k2<<<NN, 256>>>(hs, src);
    k3<<<TILES, 256, SMEM3>>>(fc1b, convw, convb, fc2b, rmsw);
    k5<<<NN*DD/256, 256>>>(hs, gamma, beta, aggw, aggb, out);
}

// round 10
// speedup vs baseline: 1.9435x; 1.9435x over previous
#include <cuda_runtime.h>
#include <cstdint>

#define NN 8192
#define DD 64
#define MAXDEG 16
#define KK 8
#define LL 17            // MAXDEG + 1
#define DIN 128          // D * EXPAND
#define EPS 1e-5f

#define ROWS2 34         // 2 nodes * 17 rows per CTA
#define HS 38            // padded row stride for transposed tiles (even, bank-staggered)

// ---------------- device scratch ----------------
__device__ float g_hflat[NN*MAXDEG*DD];
__device__ float g_hinput[NN*LL*DD];
__device__ float g_y[NN*LL*DD];
__device__ float g_bnsum[DD];
__device__ float g_bnsq[DD];
__device__ float g_w1t[64*256];           // fc1_w^T [k][ch]
__device__ float g_w2t[128*64];           // fc2_w^T [c][d]

__device__ __forceinline__ float sigm(float x) { return 1.f/(1.f+__expf(-x)); }

__device__ __forceinline__ uint64_t pack2(float lo, float hi) {
    uint64_t r; asm("mov.b64 %0, {%1,%2};" : "=l"(r) : "f"(lo), "f"(hi)); return r;
}
__device__ __forceinline__ void unpack2(uint64_t v, float& lo, float& hi) {
    asm("mov.b64 {%0,%1}, %2;" : "=f"(lo), "=f"(hi) : "l"(v));
}
__device__ __forceinline__ void fma2(uint64_t& d, uint64_t a, uint64_t b) {
    asm("fma.rn.f32x2 %0, %1, %2, %0;" : "+l"(d) : "l"(a), "l"(b));
}
__device__ __forceinline__ uint64_t add2(uint64_t a, uint64_t b) {
    uint64_t r; asm("add.rn.f32x2 %0, %1, %2;" : "=l"(r) : "l"(a), "l"(b)); return r;
}

// smem float offsets (k3): ht 64*38=2432 | xt 128*38=4864 | zt 128*38=4864 | rr 64 | bnp 512
#define FO_HT  0
#define FO_XT  2432
#define FO_ZT  7296
#define FO_RR  12160
#define FO_BNP 12224
#define SMEM3  (12736*4)

// ---------------- K0: zero BN accumulators (graph replays!) ----------------
__global__ void kz() {
    int t = threadIdx.x;
    if (t < DD) { g_bnsum[t] = 0.f; g_bnsq[t] = 0.f; }
}

// ---------------- KW: transpose weights into lane-coalesced layouts ----------------
__global__ void kw(const float* __restrict__ fc1w, const float* __restrict__ fc2w) {
    int i = blockIdx.x*256 + threadIdx.x;      // grid 64 -> 16384
    { int c = i >> 6, k = i & 63; g_w1t[k*256 + c] = fc1w[i]; }
    if (i < 64*128) { int d = i >> 7, c = i & 127; g_w2t[c*64 + d] = fc2w[i]; }
}

// ---------------- K1: message + mailbox rank-sort ----------------
__global__ void k1(const float* __restrict__ hs, const float* __restrict__ hs_e,
                   const float* __restrict__ degree, const float* __restrict__ noise) {
    int n = blockIdx.x*4 + (threadIdx.x >> 6);
    int d = threadIdx.x & 63;
    float h = hs[n*DD + d];
    float deg = __ldg(&degree[n]);
    float sc[KK];
#pragma unroll
    for (int k = 0; k < KK; k++) sc[k] = deg + __ldg(&noise[n*KK + k]);
#pragma unroll
    for (int k = 0; k < KK; k++) {
        float e = hs_e[(n*KK + k)*DD + d];
        float m = h * sigm(e);
        int r = 0;
#pragma unroll
        for (int j = 0; j < KK; j++)
            r += (sc[j] < sc[k]) || (sc[j] == sc[k] && j < k);   // stable rank
        g_hflat[n*(MAXDEG*DD) + r*DD + d] = m;
    }
#pragma unroll
    for (int j = KK; j < MAXDEG; j++)
        g_hflat[n*(MAXDEG*DD) + j*DD + d] = 0.f;
}

// ---------------- K2: (A+I) spmm gather ----------------
__global__ void k2(const float* __restrict__ hs, const int* __restrict__ src) {
    int n = blockIdx.x;
    int t = threadIdx.x;
    if (t < DD) g_hinput[n*(LL*DD) + t] = hs[n*DD + t];
    float4 a = ((const float4*)(g_hflat + n*(MAXDEG*DD)))[t];
#pragma unroll
    for (int k = 0; k < KK; k++) {
        int s = __ldg(&src[n*KK + k]);
        float4 v = ((const float4*)(g_hflat + s*(MAXDEG*DD)))[t];
        a.x += v.x; a.y += v.y; a.z += v.z; a.w += v.w;
    }
    ((float4*)(g_hinput + n*(LL*DD) + DD))[t] = a;
}

// ---------------- K3: f32x2 GatedCNN ----------------
// 4096 CTAs x 256 threads, 2 nodes/CTA (34 rows = 17 row-pairs), 2 CTAs/SM.
// fc1: thread = 1 channel, 17 packed row-pair accumulators.
// fc2: thread = (d, quarter), 5 packed pairs (overlapping coverage, benign).
__global__ void __launch_bounds__(256, 2)
k3(const float* __restrict__ fc1b, const float* __restrict__ convw,
   const float* __restrict__ convb, const float* __restrict__ fc2b,
   const float* __restrict__ rmsw) {
    extern __shared__ float sm[];
    float* ht  = sm + FO_HT;    // [64 k][HS]  transposed h, rows paired
    float* xt  = sm + FO_XT;    // [128 c][HS] fc1 x-half (bias added)
    float* zt  = sm + FO_ZT;    // [128 c][HS] silu(z) -> gated in place
    float* d2  = xt;            // [34 r][64 d] fc2 out (aliases dead xt)
    float* rr  = sm + FO_RR;
    float* bnp = sm + FO_BNP;

    int t = threadIdx.x;
    int n0 = blockIdx.x*2;
    const float* hsrc = g_hinput + (size_t)n0*(LL*DD);   // [34][64] contiguous

    // ---- stage transposed h: ht[k][r] ----
    for (int i = t; i < ROWS2*DD; i += 256) {
        int r = i >> 6, k = i & 63;
        ht[k*HS + r] = hsrc[i];
    }
    __syncthreads();

    // ---- fc1: channel c = t, 17 row-pairs, packed FMA ----
    {
        int c = t;
        uint64_t acc[17];
#pragma unroll
        for (int p = 0; p < 17; p++) acc[p] = 0ull;
#pragma unroll 4
        for (int k = 0; k < 64; k++) {
            float wv = __ldg(&g_w1t[k*256 + c]);
            uint64_t wp = pack2(wv, wv);
            const uint64_t* hp = (const uint64_t*)(ht + k*HS);
#pragma unroll
            for (int p = 0; p < 17; p++) fma2(acc[p], hp[p], wp);
        }
        float b1 = __ldg(&fc1b[c]);
        if (c < DIN) {
            uint64_t bp = pack2(b1, b1);
            uint64_t* dst = (uint64_t*)(xt + c*HS);
#pragma unroll
            for (int p = 0; p < 17; p++) dst[p] = add2(acc[p], bp);
        } else {
            uint64_t* dst = (uint64_t*)(zt + (c - DIN)*HS);
#pragma unroll
            for (int p = 0; p < 17; p++) {
                float lo, hi; unpack2(acc[p], lo, hi);
                lo += b1; hi += b1;
                dst[p] = pack2(lo*sigm(lo), hi*sigm(hi));
            }
        }
    }
    __syncthreads();

    // ---- conv + gate: c = t&127, node = t>>7, causal within node ----
    {
        int c = t & 127, nd = t >> 7;
        float cw0 = __ldg(&convw[c*4+0]), cw1 = __ldg(&convw[c*4+1]);
        float cw2 = __ldg(&convw[c*4+2]), cw3 = __ldg(&convw[c*4+3]);
        float cb  = __ldg(&convb[c]);
        const float* xr = xt + c*HS + nd*LL;
        float* gr = zt + c*HS + nd*LL;
        float xm1 = 0.f, xm2 = 0.f, xm3 = 0.f;
#pragma unroll
        for (int l = 0; l < LL; l++) {
            float x = xr[l];
            float xc = cb + x*cw3 + xm1*cw2 + xm2*cw1 + xm3*cw0;
            xm3 = xm2; xm2 = xm1; xm1 = x;
            gr[l] = xc*sigm(xc) * gr[l];
        }
    }
    __syncthreads();

    // ---- fc2: d = t&63, quarter q = t>>6 -> pairs q*4..q*4+4 (overlap benign) ----
    {
        int d = t & 63, q = t >> 6;
        int p0 = q*4;
        uint64_t acc[5];
#pragma unroll
        for (int j = 0; j < 5; j++) acc[j] = 0ull;
#pragma unroll 2
        for (int cc = 0; cc < 128; cc++) {
            float wv = __ldg(&g_w2t[cc*64 + d]);
            uint64_t wp = pack2(wv, wv);
            const uint64_t* gp = (const uint64_t*)(zt + cc*HS) + p0;
#pragma unroll
            for (int j = 0; j < 5; j++) fma2(acc[j], gp[j], wp);
        }
        __syncthreads();   // all zt reads done before d2 (xt alias region untouched; sync for rms order)
        float b2 = __ldg(&fc2b[d]);
#pragma unroll
        for (int j = 0; j < 5; j++) {
            int r = (p0 + j)*2;
            float lo, hi; unpack2(acc[j], lo, hi);
            d2[r*DD + d]     = lo + b2;
            d2[(r+1)*DD + d] = hi + b2;
        }
    }
    __syncthreads();

    // ---- rms per row (staggered reads) ----
    if (t < ROWS2) {
        const float* row = d2 + t*DD;
        float s = 0.f;
#pragma unroll
        for (int dd = 0; dd < DD; dd++) { float v = row[(dd + t) & 63]; s += v*v; }
        rr[t] = rsqrtf(s * (1.f/DD) + EPS);
    }
    __syncthreads();

    // ---- y = rmsnorm*rms_w + h_input; BN partials ----
    {
        int d = t & 63, rg = t >> 6;
        float rw = __ldg(&rmsw[d]);
        float bsum = 0.f, bsq = 0.f;
        float* ydst = g_y + (size_t)n0*(LL*DD);
#pragma unroll
        for (int r = rg; r < ROWS2; r += 4) {
            float v = d2[r*DD + d] * rr[r] * rw + hsrc[r*DD + d];
            ydst[r*DD + d] = v;
            bsum += v; bsq += v*v;
        }
        bnp[t] = bsum;
        bnp[256 + t] = bsq;
    }
    __syncthreads();
    if (t < DD) {
        float s  = bnp[t] + bnp[t+64] + bnp[t+128] + bnp[t+192];
        float s2 = bnp[256+t] + bnp[256+t+64] + bnp[256+t+128] + bnp[256+t+192];
        atomicAdd(&g_bnsum[t], s);
        atomicAdd(&g_bnsq[t], s2);
    }
}

// ---------------- K5: BN apply + ReLU6 + L-aggregation + residual ----------------
__global__ void k5(const float* __restrict__ hs, const float* __restrict__ gamma,
                   const float* __restrict__ beta, const float* __restrict__ aggw,
                   const float* __restrict__ aggb, float* __restrict__ out) {
    int idx = blockIdx.x*256 + threadIdx.x;
    int d = idx & 63;
    float cnt = (float)(NN*LL);
    float mean = g_bnsum[d] / cnt;
    float var  = g_bnsq[d] / cnt - mean*mean;
    float is = rsqrtf(var + EPS);
    float ga = __ldg(&gamma[d]) * is;
    float be = __ldg(&beta[d]) - mean * ga;
    const float* yrow = g_y + (size_t)(idx >> 6)*(LL*DD);
    float s = __ldg(&aggb[0]);
#pragma unroll
    for (int l = 0; l < LL; l++) {
        float v = yrow[l*DD + d] * ga + be;
        v = fminf(fmaxf(v, 0.f), 6.f);
        s += v * __ldg(&aggw[l]);
    }
    out[idx] = s + hs[idx];
}

// ---------------- host ----------------
extern "C" void kernel_launch(void* const* d_in, const int* in_sizes, int n_in,
                              void* d_out, int out_size) {
    const float* hs     = (const float*)d_in[0];
    const float* hs_e   = (const float*)d_in[1];
    const float* degree = (const float*)d_in[2];
    const float* noise  = (const float*)d_in[3];
    const float* fc1w   = (const float*)d_in[4];
    const float* fc1b   = (const float*)d_in[5];
    const float* convw  = (const float*)d_in[6];
    const float* convb  = (const float*)d_in[7];
    const float* fc2w   = (const float*)d_in[8];
    const float* fc2b   = (const float*)d_in[9];
    const float* rmsw   = (const float*)d_in[10];
    const float* gamma  = (const float*)d_in[11];
    const float* beta   = (const float*)d_in[12];
    const float* aggw   = (const float*)d_in[13];
    const float* aggb   = (const float*)d_in[14];
    const int*   src    = (const int*)d_in[15];
    float* out = (float*)d_out;

    cudaFuncSetAttribute(k3, cudaFuncAttributeMaxDynamicSharedMemorySize, SMEM3);

    kz<<<1, 64>>>();
    kw<<<64, 256>>>(fc1w, fc2w);
    k1<<<NN/4, 256>>>(hs, hs_e, degree, noise);
    k2<<<NN, 256>>>(hs, src);
    k3<<<NN/2, 256, SMEM3>>>(fc1b, convw, convb, fc2b, rmsw);
    k5<<<NN*DD/256, 256>>>(hs, gamma, beta, aggw, aggb, out);
}

// round 11
// speedup vs baseline: 3.8920x; 2.0026x over previous
#include <cuda_runtime.h>
#include <cstdint>

#define NN 8192
#define DD 64
#define KK 8
#define LL 17
#define DIN 128
#define EPS 1e-5f
#define R9 9             // nonzero h_input rows
#define R12 12           // rows needing full compute

// ---------------- device scratch ----------------
__device__ float g_hflat[NN*KK*DD];       // [N,8,64] sorted mailbox (real slots only)
__device__ float g_h9[NN*R9*DD];          // [N,9,64] h_input nonzero rows
__device__ float g_y[NN*R12*DD];          // [N,12,64]
__device__ float g_yc[DD];                // constant tail row (l=12..16)
__device__ float g_bnsum[DD];
__device__ float g_bnsq[DD];
__device__ float g_w1t[64*256];           // fc1_w^T [k][ch]
__device__ float g_w2t[128*64];           // fc2_w^T [c][d]

__device__ __forceinline__ float sigm(float x) { return 1.f/(1.f+__expf(-x)); }

// ---------------- K0: zero BN accumulators (graph replays!) ----------------
__global__ void kz() {
    int t = threadIdx.x;
    if (t < DD) { g_bnsum[t] = 0.f; g_bnsq[t] = 0.f; }
}

// ---------------- KW: transpose weights ----------------
__global__ void kw(const float* __restrict__ fc1w, const float* __restrict__ fc2w) {
    int i = blockIdx.x*256 + threadIdx.x;      // grid 64
    { int c = i >> 6, k = i & 63; g_w1t[k*256 + c] = fc1w[i]; }
    if (i < 64*128) { int d = i >> 7, c = i & 127; g_w2t[c*64 + d] = fc2w[i]; }
}

// ---------------- KC: constant tail row yc (node-independent, rows 12..16) ----------------
__global__ void kc(const float* __restrict__ fc1b, const float* __restrict__ convw,
                   const float* __restrict__ convb, const float* __restrict__ fc2b,
                   const float* __restrict__ rmsw) {
    __shared__ float gc[128];
    __shared__ float oc[64];
    int t = threadIdx.x;   // 128
    {
        float cwsum = convw[t*4] + convw[t*4+1] + convw[t*4+2] + convw[t*4+3];
        float xc = convb[t] + fc1b[t]*cwsum;
        float z = fc1b[DIN + t];
        gc[t] = xc*sigm(xc) * (z*sigm(z));
    }
    __syncthreads();
    if (t < 64) {
        float s = fc2b[t];
        for (int c = 0; c < 128; c++) s += g_w2t[c*64 + t]*gc[c];
        oc[t] = s;
    }
    __syncthreads();
    if (t < 64) {
        float ss = 0.f;
        for (int d = 0; d < 64; d++) ss += oc[d]*oc[d];
        g_yc[t] = oc[t] * rsqrtf(ss*(1.f/DD) + EPS) * rmsw[t];
    }
}

// ---------------- K1: message + mailbox rank-sort (8 real slots) ----------------
__global__ void k1(const float* __restrict__ hs, const float* __restrict__ hs_e,
                   const float* __restrict__ degree, const float* __restrict__ noise) {
    int n = blockIdx.x*4 + (threadIdx.x >> 6);
    int d = threadIdx.x & 63;
    float h = hs[n*DD + d];
    float deg = __ldg(&degree[n]);
    float sc[KK];
#pragma unroll
    for (int k = 0; k < KK; k++) sc[k] = deg + __ldg(&noise[n*KK + k]);
#pragma unroll
    for (int k = 0; k < KK; k++) {
        float e = hs_e[(n*KK + k)*DD + d];
        float m = h * sigm(e);
        int r = 0;
#pragma unroll
        for (int j = 0; j < KK; j++)
            r += (sc[j] < sc[k]) || (sc[j] == sc[k] && j < k);   // stable rank
        g_hflat[n*(KK*DD) + r*DD + d] = m;
    }
}

// ---------------- K2: (A+I) spmm gather (512-wide) + build h9 ----------------
__global__ void k2(const float* __restrict__ hs, const int* __restrict__ src) {
    int n = blockIdx.x;
    int t = threadIdx.x;   // 128
    if (t < DD) g_h9[n*(R9*DD) + t] = hs[n*DD + t];       // slot 0 = hs
    float4 a = ((const float4*)(g_hflat + n*(KK*DD)))[t];
#pragma unroll
    for (int k = 0; k < KK; k++) {
        int s = __ldg(&src[n*KK + k]);
        float4 v = ((const float4*)(g_hflat + (size_t)s*(KK*DD)))[t];
        a.x += v.x; a.y += v.y; a.z += v.z; a.w += v.w;
    }
    ((float4*)(g_h9 + n*(R9*DD) + DD))[t] = a;            // slots 1..8
}

// ---------------- K3: GatedCNN on 9 real rows / 12 output rows ----------------
// 4096 CTAs x 256 threads, 2 nodes/CTA, 128 thr/node.
// fc1: thread = 2 channels x 9 rows. fc2: thread = 1 d x 6 rows.
__global__ void __launch_bounds__(256)
k3(const float* __restrict__ fc1b, const float* __restrict__ convw,
   const float* __restrict__ convb, const float* __restrict__ fc2b,
   const float* __restrict__ rmsw) {
    __shared__ float h[2*R9*DD];       // [nd][l][k]      4608 B
    __shared__ float a[2*R9*256];      // [nd][l][ch]    18432 B
    __shared__ float gbuf[2*R12*DIN];  // [nd][l][c]     12288 B
    __shared__ float ob[2*R12*DD];     // [nd][l][d]      6144 B
    __shared__ float rr[2*R12];
    __shared__ float bnp[512];

    int t = threadIdx.x;
    int nd = t >> 7, u = t & 127;
    int n0 = blockIdx.x*2;

    // stage h (2 nodes x 9 x 64)
    {
        const float4* s4 = (const float4*)(g_h9 + (size_t)n0*(R9*DD));
        float4* d4 = (float4*)h;
#pragma unroll
        for (int i = t; i < 2*R9*DD/4; i += 256) d4[i] = s4[i];
    }
    __syncthreads();

    // ---- fc1: channels 2u, 2u+1; rows 0..8 ----
    {
        float acc0[R9], acc1[R9];
#pragma unroll
        for (int l = 0; l < R9; l++) { acc0[l] = 0.f; acc1[l] = 0.f; }
        const float* hrow = h + nd*(R9*DD);
#pragma unroll 1
        for (int k4 = 0; k4 < 16; k4++) {
            float2 w0 = *(const float2*)&g_w1t[(k4*4+0)*256 + 2*u];
            float2 w1 = *(const float2*)&g_w1t[(k4*4+1)*256 + 2*u];
            float2 w2 = *(const float2*)&g_w1t[(k4*4+2)*256 + 2*u];
            float2 w3 = *(const float2*)&g_w1t[(k4*4+3)*256 + 2*u];
#pragma unroll
            for (int l = 0; l < R9; l++) {
                float4 h4 = *(const float4*)&hrow[l*DD + k4*4];
                acc0[l] += h4.x*w0.x + h4.y*w1.x + h4.z*w2.x + h4.w*w3.x;
                acc1[l] += h4.x*w0.y + h4.y*w1.y + h4.z*w2.y + h4.w*w3.y;
            }
        }
        float* arow = a + nd*(R9*256);
#pragma unroll
        for (int l = 0; l < R9; l++) {
            float2 v; v.x = acc0[l]; v.y = acc1[l];
            *(float2*)&arow[l*256 + 2*u] = v;
        }
    }
    __syncthreads();

    // ---- conv + gate: rows 0..11 (rows >8 use bias-only x/z) ----
    {
        int c = u;
        float cw0 = __ldg(&convw[c*4+0]), cw1 = __ldg(&convw[c*4+1]);
        float cw2 = __ldg(&convw[c*4+2]), cw3 = __ldg(&convw[c*4+3]);
        float cb  = __ldg(&convb[c]);
        float b1x = __ldg(&fc1b[c]);
        float b1z = __ldg(&fc1b[DIN + c]);
        const float* arow = a + nd*(R9*256);
        float* grow = gbuf + nd*(R12*DIN);
        float xm1 = 0.f, xm2 = 0.f, xm3 = 0.f;
#pragma unroll
        for (int l = 0; l < R12; l++) {
            float x = (l <= 8) ? (arow[l*256 + c] + b1x) : b1x;
            float xc = cb + x*cw3 + xm1*cw2 + xm2*cw1 + xm3*cw0;
            xm3 = xm2; xm2 = xm1; xm1 = x;
            float z = (l <= 8) ? (arow[l*256 + 128 + c] + b1z) : b1z;
            grow[l*DIN + c] = xc*sigm(xc) * (z*sigm(z));
        }
    }
    __syncthreads();

    // ---- fc2: d = u&63, rows (u>>6)*6 .. +5 ----
    {
        int d = u & 63, hh = u >> 6;
        float acc2[6];
#pragma unroll
        for (int j = 0; j < 6; j++) acc2[j] = 0.f;
        const float* grow = gbuf + nd*(R12*DIN) + hh*6*DIN;
#pragma unroll 1
        for (int c4 = 0; c4 < 32; c4++) {
            float wa = __ldg(&g_w2t[(c4*4+0)*64 + d]);
            float wb = __ldg(&g_w2t[(c4*4+1)*64 + d]);
            float wc = __ldg(&g_w2t[(c4*4+2)*64 + d]);
            float wd = __ldg(&g_w2t[(c4*4+3)*64 + d]);
#pragma unroll
            for (int j = 0; j < 6; j++) {
                float4 g4 = *(const float4*)&grow[j*DIN + c4*4];
                acc2[j] += g4.x*wa + g4.y*wb + g4.z*wc + g4.w*wd;
            }
        }
        float b2 = __ldg(&fc2b[d]);
        float* obrow = ob + nd*(R12*DD) + hh*6*DD;
#pragma unroll
        for (int j = 0; j < 6; j++) obrow[j*DD + d] = acc2[j] + b2;
    }
    __syncthreads();

    // ---- rms per row (24 rows, staggered reads) ----
    if (t < 2*R12) {
        int nn_ = t / R12, l = t % R12;
        const float* row = ob + nn_*(R12*DD) + l*DD;
        float s = 0.f;
#pragma unroll
        for (int dd = 0; dd < DD; dd++) { float v = row[(dd + t) & 63]; s += v*v; }
        rr[t] = rsqrtf(s * (1.f/DD) + EPS);
    }
    __syncthreads();

    // ---- y = rmsnorm*rms_w + h_input (rows>8: residual 0); BN partials ----
    {
        int d = u & 63, hh = u >> 6;
        float rw = __ldg(&rmsw[d]);
        float bsum = 0.f, bsq = 0.f;
        float* ydst = g_y + (size_t)(n0 + nd)*(R12*DD);
        const float* hrow = h + nd*(R9*DD);
#pragma unroll
        for (int j = 0; j < 6; j++) {
            int l = hh*6 + j;
            float res = (l <= 8) ? hrow[l*DD + d] : 0.f;
            float v = ob[nd*(R12*DD) + l*DD + d] * rr[nd*R12 + l] * rw + res;
            ydst[l*DD + d] = v;
            bsum += v; bsq += v*v;
        }
        bnp[t] = bsum; bnp[256 + t] = bsq;
    }
    __syncthreads();
    if (t < DD) {
        atomicAdd(&g_bnsum[t], bnp[t] + bnp[t+64] + bnp[t+128] + bnp[t+192]);
    } else if (t < 2*DD) {
        int d = t - DD;
        atomicAdd(&g_bnsq[d], bnp[256+d] + bnp[256+d+64] + bnp[256+d+128] + bnp[256+d+192]);
    }
}

// ---------------- K5: BN apply + ReLU6 + L-agg (12 rows + constant tail) ----------------
__global__ void k5(const float* __restrict__ hs, const float* __restrict__ gamma,
                   const float* __restrict__ beta, const float* __restrict__ aggw,
                   const float* __restrict__ aggb, float* __restrict__ out) {
    int idx = blockIdx.x*256 + threadIdx.x;
    int d = idx & 63;
    float cnt = (float)(NN*LL);
    float yc = g_yc[d];
    float bs = g_bnsum[d] + 5.f*NN*yc;
    float bq = g_bnsq[d]  + 5.f*NN*yc*yc;
    float mean = bs / cnt;
    float var  = bq / cnt - mean*mean;
    float is = rsqrtf(var + EPS);
    float ga = __ldg(&gamma[d]) * is;
    float be = __ldg(&beta[d]) - mean * ga;
    const float* yrow = g_y + (size_t)(idx >> 6)*(R12*DD);
    float s = __ldg(&aggb[0]);
#pragma unroll
    for (int l = 0; l < R12; l++) {
        float v = yrow[l*DD + d] * ga + be;
        v = fminf(fmaxf(v, 0.f), 6.f);
        s += v * __ldg(&aggw[l]);
    }
    {
        float vc = fminf(fmaxf(yc * ga + be, 0.f), 6.f);
        float tailw = __ldg(&aggw[12]) + __ldg(&aggw[13]) + __ldg(&aggw[14])
                    + __ldg(&aggw[15]) + __ldg(&aggw[16]);
        s += vc * tailw;
    }
    out[idx] = s + hs[idx];
}

// ---------------- host ----------------
extern "C" void kernel_launch(void* const* d_in, const int* in_sizes, int n_in,
                              void* d_out, int out_size) {
    const float* hs     = (const float*)d_in[0];
    const float* hs_e   = (const float*)d_in[1];
    const float* degree = (const float*)d_in[2];
    const float* noise  = (const float*)d_in[3];
    const float* fc1w   = (const float*)d_in[4];
    const float* fc1b   = (const float*)d_in[5];
    const float* convw  = (const float*)d_in[6];
    const float* convb  = (const float*)d_in[7];
    const float* fc2w   = (const float*)d_in[8];
    const float* fc2b   = (const float*)d_in[9];
    const float* rmsw   = (const float*)d_in[10];
    const float* gamma  = (const float*)d_in[11];
    const float* beta   = (const float*)d_in[12];
    const float* aggw   = (const float*)d_in[13];
    const float* aggb   = (const float*)d_in[14];
    const int*   src    = (const int*)d_in[15];
    float* out = (float*)d_out;

    kz<<<1, 64>>>();
    kw<<<64, 256>>>(fc1w, fc2w);
    kc<<<1, 128>>>(fc1b, convw, convb, fc2b, rmsw);
    k1<<<NN/4, 256>>>(hs, hs_e, degree, noise);
    k2<<<NN, 128>>>(hs, src);
    k3<<<NN/2, 256>>>(fc1b, convw, convb, fc2b, rmsw);
    k5<<<NN*DD/256, 256>>>(hs, gamma, beta, aggw, aggb, out);
}

// round 12
// speedup vs baseline: 3.8983x; 1.0016x over previous
#include <cuda_runtime.h>
#include <cstdint>

#define NN 8192
#define DD 64
#define KK 8
#define LL 17
#define DIN 128
#define EPS 1e-5f
#define R9 9             // nonzero h_input rows
#define R12 12           // rows needing full compute

// ---------------- device scratch ----------------
__device__ float g_hflat[NN*KK*DD];       // [N,8,64] sorted mailbox (real slots only)
__device__ float g_h9[NN*R9*DD];          // [N,9,64] h_input nonzero rows
__device__ float g_y[NN*R12*DD];          // [N,12,64]
__device__ float g_yc[DD];                // constant tail row (l=12..16)
__device__ float g_bnsum[DD];
__device__ float g_bnsq[DD];
__device__ float g_w1t[64*256];           // fc1_w^T [k][ch]
__device__ float g_w2t[128*64];           // fc2_w^T [c][d]

__device__ __forceinline__ float sigm(float x) { return 1.f/(1.f+__expf(-x)); }

// smem float offsets (k3): h 4*9*64 | a 4*9*256 | g 4*12*128 | ob 4*12*64 | rr 48 | bnp 512
#define FO_H   0
#define FO_A   2304
#define FO_G   11520
#define FO_OB  17664
#define FO_RR  20736
#define FO_BNP 20784
#define SMEM3  (21296*4)

// ---------------- K0: zero BN accumulators (graph replays!) ----------------
__global__ void kz() {
    int t = threadIdx.x;
    if (t < DD) { g_bnsum[t] = 0.f; g_bnsq[t] = 0.f; }
}

// ---------------- KW: transpose weights ----------------
__global__ void kw(const float* __restrict__ fc1w, const float* __restrict__ fc2w) {
    int i = blockIdx.x*256 + threadIdx.x;      // grid 64
    { int c = i >> 6, k = i & 63; g_w1t[k*256 + c] = fc1w[i]; }
    if (i < 64*128) { int d = i >> 7, c = i & 127; g_w2t[c*64 + d] = fc2w[i]; }
}

// ---------------- KC: constant tail row yc (node-independent, rows 12..16) ----------------
__global__ void kc(const float* __restrict__ fc1b, const float* __restrict__ convw,
                   const float* __restrict__ convb, const float* __restrict__ fc2b,
                   const float* __restrict__ rmsw) {
    __shared__ float gc[128];
    __shared__ float oc[64];
    int t = threadIdx.x;   // 128
    {
        float cwsum = convw[t*4] + convw[t*4+1] + convw[t*4+2] + convw[t*4+3];
        float xc = convb[t] + fc1b[t]*cwsum;
        float z = fc1b[DIN + t];
        gc[t] = xc*sigm(xc) * (z*sigm(z));
    }
    __syncthreads();
    if (t < 64) {
        float s = fc2b[t];
        for (int c = 0; c < 128; c++) s += g_w2t[c*64 + t]*gc[c];
        oc[t] = s;
    }
    __syncthreads();
    if (t < 64) {
        float ss = 0.f;
        for (int d = 0; d < 64; d++) ss += oc[d]*oc[d];
        g_yc[t] = oc[t] * rsqrtf(ss*(1.f/DD) + EPS) * rmsw[t];
    }
}

// ---------------- K1: message + mailbox rank-sort (8 real slots) ----------------
__global__ void k1(const float* __restrict__ hs, const float* __restrict__ hs_e,
                   const float* __restrict__ degree, const float* __restrict__ noise) {
    int n = blockIdx.x*4 + (threadIdx.x >> 6);
    int d = threadIdx.x & 63;
    float h = hs[n*DD + d];
    float deg = __ldg(&degree[n]);
    float sc[KK];
#pragma unroll
    for (int k = 0; k < KK; k++) sc[k] = deg + __ldg(&noise[n*KK + k]);
#pragma unroll
    for (int k = 0; k < KK; k++) {
        float e = hs_e[(n*KK + k)*DD + d];
        float m = h * sigm(e);
        int r = 0;
#pragma unroll
        for (int j = 0; j < KK; j++)
            r += (sc[j] < sc[k]) || (sc[j] == sc[k] && j < k);   // stable rank
        g_hflat[n*(KK*DD) + r*DD + d] = m;
    }
}

// ---------------- K2: (A+I) spmm gather (512-wide) + build h9 ----------------
__global__ void k2(const float* __restrict__ hs, const int* __restrict__ src) {
    int n = blockIdx.x;
    int t = threadIdx.x;   // 128
    if (t < DD) g_h9[n*(R9*DD) + t] = hs[n*DD + t];       // slot 0 = hs
    float4 a = ((const float4*)(g_hflat + n*(KK*DD)))[t];
#pragma unroll
    for (int k = 0; k < KK; k++) {
        int s = __ldg(&src[n*KK + k]);
        float4 v = ((const float4*)(g_hflat + (size_t)s*(KK*DD)))[t];
        a.x += v.x; a.y += v.y; a.z += v.z; a.w += v.w;
    }
    ((float4*)(g_h9 + n*(R9*DD) + DD))[t] = a;            // slots 1..8
}

// ---------------- K3: GatedCNN, 4 nodes/CTA ----------------
// 2048 CTAs x 256 threads. fc1: 64 thr/node, 4 ch x 9 rows each.
// fc2: 64 thr/node, 1 d x 12 rows each.
__global__ void __launch_bounds__(256)
k3(const float* __restrict__ fc1b, const float* __restrict__ convw,
   const float* __restrict__ convb, const float* __restrict__ fc2b,
   const float* __restrict__ rmsw) {
    extern __shared__ float sm[];
    float* h    = sm + FO_H;     // [4 nd][9 l][64 k]
    float* a    = sm + FO_A;     // [4 nd][9 l][256 ch]
    float* gbuf = sm + FO_G;     // [4 nd][12 l][128 c]
    float* ob   = sm + FO_OB;    // [4 nd][12 l][64 d]
    float* rr   = sm + FO_RR;    // [48]
    float* bnp  = sm + FO_BNP;   // [512]

    int t = threadIdx.x;
    int n0 = blockIdx.x*4;

    // stage h (4 nodes x 9 x 64)
    {
        const float4* s4 = (const float4*)(g_h9 + (size_t)n0*(R9*DD));
        float4* d4 = (float4*)h;
#pragma unroll
        for (int i = t; i < 4*R9*DD/4; i += 256) d4[i] = s4[i];
    }
    __syncthreads();

    // ---- fc1: nd = t>>6, channels 4u..4u+3 (u = t&63), rows 0..8 ----
    {
        int nd = t >> 6, u = t & 63;
        float acc[R9][4];
#pragma unroll
        for (int l = 0; l < R9; l++) { acc[l][0]=0; acc[l][1]=0; acc[l][2]=0; acc[l][3]=0; }
        const float* hrow = h + nd*(R9*DD);
#pragma unroll 2
        for (int k4 = 0; k4 < 16; k4++) {
            float4 w0 = *(const float4*)&g_w1t[(k4*4+0)*256 + 4*u];
            float4 w1 = *(const float4*)&g_w1t[(k4*4+1)*256 + 4*u];
            float4 w2 = *(const float4*)&g_w1t[(k4*4+2)*256 + 4*u];
            float4 w3 = *(const float4*)&g_w1t[(k4*4+3)*256 + 4*u];
#pragma unroll
            for (int l = 0; l < R9; l++) {
                float4 h4 = *(const float4*)&hrow[l*DD + k4*4];
                acc[l][0] += h4.x*w0.x + h4.y*w1.x + h4.z*w2.x + h4.w*w3.x;
                acc[l][1] += h4.x*w0.y + h4.y*w1.y + h4.z*w2.y + h4.w*w3.y;
                acc[l][2] += h4.x*w0.z + h4.y*w1.z + h4.z*w2.z + h4.w*w3.z;
                acc[l][3] += h4.x*w0.w + h4.y*w1.w + h4.z*w2.w + h4.w*w3.w;
            }
        }
        float* arow = a + nd*(R9*256);
#pragma unroll
        for (int l = 0; l < R9; l++)
            *(float4*)&arow[l*256 + 4*u] = *(float4*)acc[l];
    }
    __syncthreads();

    // ---- conv + gate: c = t&127, nodes (t>>7) and (t>>7)+2; rows 0..11 ----
    {
        int c = t & 127;
        float cw0 = __ldg(&convw[c*4+0]), cw1 = __ldg(&convw[c*4+1]);
        float cw2 = __ldg(&convw[c*4+2]), cw3 = __ldg(&convw[c*4+3]);
        float cb  = __ldg(&convb[c]);
        float b1x = __ldg(&fc1b[c]);
        float b1z = __ldg(&fc1b[DIN + c]);
#pragma unroll
        for (int pass = 0; pass < 2; pass++) {
            int nd = (t >> 7) + pass*2;
            const float* arow = a + nd*(R9*256);
            float* grow = gbuf + nd*(R12*DIN);
            float xm1 = 0.f, xm2 = 0.f, xm3 = 0.f;
#pragma unroll
            for (int l = 0; l < R12; l++) {
                float x = (l <= 8) ? (arow[l*256 + c] + b1x) : b1x;
                float xc = cb + x*cw3 + xm1*cw2 + xm2*cw1 + xm3*cw0;
                xm3 = xm2; xm2 = xm1; xm1 = x;
                float z = (l <= 8) ? (arow[l*256 + 128 + c] + b1z) : b1z;
                grow[l*DIN + c] = xc*sigm(xc) * (z*sigm(z));
            }
        }
    }
    __syncthreads();

    // ---- fc2: nd = t>>6, d = t&63, all 12 rows ----
    {
        int nd = t >> 6, d = t & 63;
        float acc2[R12];
#pragma unroll
        for (int j = 0; j < R12; j++) acc2[j] = 0.f;
        const float* grow = gbuf + nd*(R12*DIN);
#pragma unroll 2
        for (int c4 = 0; c4 < 32; c4++) {
            float wa = __ldg(&g_w2t[(c4*4+0)*64 + d]);
            float wb = __ldg(&g_w2t[(c4*4+1)*64 + d]);
            float wc = __ldg(&g_w2t[(c4*4+2)*64 + d]);
            float wd = __ldg(&g_w2t[(c4*4+3)*64 + d]);
#pragma unroll
            for (int j = 0; j < R12; j++) {
                float4 g4 = *(const float4*)&grow[j*DIN + c4*4];
                acc2[j] += g4.x*wa + g4.y*wb + g4.z*wc + g4.w*wd;
            }
        }
        float b2 = __ldg(&fc2b[d]);
        float* obrow = ob + nd*(R12*DD);
#pragma unroll
        for (int j = 0; j < R12; j++) obrow[j*DD + d] = acc2[j] + b2;
    }
    __syncthreads();

    // ---- rms per row (48 rows, staggered reads) ----
    if (t < 4*R12) {
        int nn_ = t / R12, l = t % R12;
        const float* row = ob + nn_*(R12*DD) + l*DD;
        float s = 0.f;
#pragma unroll
        for (int dd = 0; dd < DD; dd++) { float v = row[(dd + t) & 63]; s += v*v; }
        rr[t] = rsqrtf(s * (1.f/DD) + EPS);
    }
    __syncthreads();

    // ---- y = rmsnorm*rms_w + h_input (rows>8: residual 0); BN partials ----
    {
        int nd = t >> 6, d = t & 63;
        float rw = __ldg(&rmsw[d]);
        float bsum = 0.f, bsq = 0.f;
        float* ydst = g_y + (size_t)(n0 + nd)*(R12*DD);
        const float* hrow = h + nd*(R9*DD);
        const float* obrow = ob + nd*(R12*DD);
#pragma unroll
        for (int l = 0; l < R12; l++) {
            float res = (l <= 8) ? hrow[l*DD + d] : 0.f;
            float v = obrow[l*DD + d] * rr[nd*R12 + l] * rw + res;
            ydst[l*DD + d] = v;
            bsum += v; bsq += v*v;
        }
        bnp[t] = bsum; bnp[256 + t] = bsq;
    }
    __syncthreads();
    if (t < DD) {
        atomicAdd(&g_bnsum[t], bnp[t] + bnp[t+64] + bnp[t+128] + bnp[t+192]);
    } else if (t < 2*DD) {
        int d = t - DD;
        atomicAdd(&g_bnsq[d], bnp[256+d] + bnp[256+d+64] + bnp[256+d+128] + bnp[256+d+192]);
    }
}

// ---------------- K5: BN apply + ReLU6 + L-agg (12 rows + constant tail) ----------------
__global__ void k5(const float* __restrict__ hs, const float* __restrict__ gamma,
                   const float* __restrict__ beta, const float* __restrict__ aggw,
                   const float* __restrict__ aggb, float* __restrict__ out) {
    int idx = blockIdx.x*256 + threadIdx.x;
    int d = idx & 63;
    float cnt = (float)(NN*LL);
    float yc = g_yc[d];
    float bs = g_bnsum[d] + 5.f*NN*yc;
    float bq = g_bnsq[d]  + 5.f*NN*yc*yc;
    float mean = bs / cnt;
    float var  = bq / cnt - mean*mean;
    float is = rsqrtf(var + EPS);
    float ga = __ldg(&gamma[d]) * is;
    float be = __ldg(&beta[d]) - mean * ga;
    const float* yrow = g_y + (size_t)(idx >> 6)*(R12*DD);
    float s = __ldg(&aggb[0]);
#pragma unroll
    for (int l = 0; l < R12; l++) {
        float v = yrow[l*DD + d] * ga + be;
        v = fminf(fmaxf(v, 0.f), 6.f);
        s += v * __ldg(&aggw[l]);
    }
    {
        float vc = fminf(fmaxf(yc * ga + be, 0.f), 6.f);
        float tailw = __ldg(&aggw[12]) + __ldg(&aggw[13]) + __ldg(&aggw[14])
                    + __ldg(&aggw[15]) + __ldg(&aggw[16]);
        s += vc * tailw;
    }
    out[idx] = s + hs[idx];
}

// ---------------- host ----------------
extern "C" void kernel_launch(void* const* d_in, const int* in_sizes, int n_in,
                              void* d_out, int out_size) {
    const float* hs     = (const float*)d_in[0];
    const float* hs_e   = (const float*)d_in[1];
    const float* degree = (const float*)d_in[2];
    const float* noise  = (const float*)d_in[3];
    const float* fc1w   = (const float*)d_in[4];
    const float* fc1b   = (const float*)d_in[5];
    const float* convw  = (const float*)d_in[6];
    const float* convb  = (const float*)d_in[7];
    const float* fc2w   = (const float*)d_in[8];
    const float* fc2b   = (const float*)d_in[9];
    const float* rmsw   = (const float*)d_in[10];
    const float* gamma  = (const float*)d_in[11];
    const float* beta   = (const float*)d_in[12];
    const float* aggw   = (const float*)d_in[13];
    const float* aggb   = (const float*)d_in[14];
    const int*   src    = (const int*)d_in[15];
    float* out = (float*)d_out;

    cudaFuncSetAttribute(k3, cudaFuncAttributeMaxDynamicSharedMemorySize, SMEM3);

    kz<<<1, 64>>>();
    kw<<<64, 256>>>(fc1w, fc2w);
    kc<<<1, 128>>>(fc1b, convw, convb, fc2b, rmsw);
    k1<<<NN/4, 256>>>(hs, hs_e, degree, noise);
    k2<<<NN, 128>>>(hs, src);
    k3<<<NN/4, 256, SMEM3>>>(fc1b, convw, convb, fc2b, rmsw);
    k5<<<NN*DD/256, 256>>>(hs, gamma, beta, aggw, aggb, out);
}